// round 8
// baseline (speedup 1.0000x reference)
#include <cuda_runtime.h>
#include <cuda_fp16.h>
#include <math.h>

#define Nn 500000
#define Ee 16000000
#define Gg 5000
#define DIMc 10
#define FINc 64
#define RSTRIDE 16                                 // halves per feature row (32 B)
#define CSTR 128                                   // fixed CSR slots per node
#define DEGMAX (CSTR - 8)

// ---------- static device scratch (all state returns to initial value each call) ----------
__device__ __align__(16) __half g_ha[((size_t)Nn + 1) * RSTRIDE];
__device__ __align__(16) __half g_hb[((size_t)Nn + 1) * RSTRIDE];
__device__ int   g_cursor[Nn + 1];                 // zero before scatter; re-zeroed in proj1
__device__ __align__(16) int g_csr[((size_t)Nn + 1) * CSTR];
__device__ int   g_perm[Nn];                       // node id | (deg << 20)
__device__ int   g_dbin[256];                      // zero; re-zeroed in post's last block
__device__ int   g_dcur[256];                      // recomputed every call
__device__ int   g_done;                           // zero; re-zeroed in post's last block
__device__ float g_sacc[Gg];                       // zero; re-zeroed in final
__device__ float g_cnt[Gg];                        // zero; re-zeroed in final

// ---------- 1: scatter edges into fixed-stride CSR (2 edges/thread — proven fastest) ----------
__global__ void k_scatter(const int* __restrict__ src, const int* __restrict__ dst) {
    int e2 = blockIdx.x * blockDim.x + threadIdx.x;   // Ee % 2 == 0
    if ((size_t)e2 * 2 >= Ee) return;
    int2 d = __ldg(reinterpret_cast<const int2*>(dst) + e2);
    int2 s = __ldg(reinterpret_cast<const int2*>(src) + e2);
    int p0 = atomicAdd(&g_cursor[d.x], 1);
    g_csr[(size_t)d.x * CSTR + min(p0, CSTR - 1)] = s.x;
    int p1 = atomicAdd(&g_cursor[d.y], 1);
    g_csr[(size_t)d.y * CSTR + min(p1, CSTR - 1)] = s.y;
}

// ---------- 2: per-node post: pad CSR rows + degree-bin hist; last block scans bins ----------
__global__ void k_post() {
    __shared__ int shist[256];
    __shared__ int slast;
    int t = threadIdx.x;                 // blockDim == 256
    shist[t] = 0;
    __syncthreads();
    int i = blockIdx.x * blockDim.x + t;
    if (i < Nn) {
        int d = min(g_cursor[i], DEGMAX);
        atomicAdd(&shist[d], 1);
        int pd = (d + 7) & ~7;
        size_t base = (size_t)i * CSTR;
        for (int q = d; q < pd; q++) g_csr[base + q] = Nn;   // dummy zero row
    }
    __syncthreads();
    if (shist[t]) atomicAdd(&g_dbin[t], shist[t]);
    __threadfence();                     // release dbin updates
    __syncthreads();
    if (t == 0) slast = (atomicAdd(&g_done, 1) == (int)gridDim.x - 1) ? 1 : 0;
    __syncthreads();
    if (slast) {                         // last arriving block: scan bins, reset state
        __threadfence();                 // acquire all dbin updates
        __shared__ int sb[256];
        int v = g_dbin[t];
        sb[t] = v;
        __syncthreads();
        #pragma unroll
        for (int off = 1; off < 256; off <<= 1) {
            int q = (t >= off) ? sb[t - off] : 0;
            __syncthreads();
            sb[t] += q;
            __syncthreads();
        }
        g_dcur[t] = sb[t] - v;           // exclusive bucket base
        g_dbin[t] = 0;                   // reset for next call
        if (t == 0) g_done = 0;
    }
}

// ---------- helpers ----------
__device__ __forceinline__ void hadd4(uint4& a, const uint4 b) {
    *reinterpret_cast<__half2*>(&a.x) = __hadd2(*reinterpret_cast<const __half2*>(&a.x),
                                                *reinterpret_cast<const __half2*>(&b.x));
    *reinterpret_cast<__half2*>(&a.y) = __hadd2(*reinterpret_cast<const __half2*>(&a.y),
                                                *reinterpret_cast<const __half2*>(&b.y));
    *reinterpret_cast<__half2*>(&a.z) = __hadd2(*reinterpret_cast<const __half2*>(&a.z),
                                                *reinterpret_cast<const __half2*>(&b.z));
    *reinterpret_cast<__half2*>(&a.w) = __hadd2(*reinterpret_cast<const __half2*>(&a.w),
                                                *reinterpret_cast<const __half2*>(&b.w));
}

__device__ __forceinline__ void add8(float* acc, uint4 v) {
    float2 f;
    f = __half22float2(*reinterpret_cast<__half2*>(&v.x)); acc[0] += f.x; acc[1] += f.y;
    f = __half22float2(*reinterpret_cast<__half2*>(&v.y)); acc[2] += f.x; acc[3] += f.y;
    f = __half22float2(*reinterpret_cast<__half2*>(&v.z)); acc[4] += f.x; acc[5] += f.y;
    f = __half22float2(*reinterpret_cast<__half2*>(&v.w)); acc[6] += f.x; acc[7] += f.y;
}

__device__ __forceinline__ void store_row10(__half* row, const float* y) {
    __half2 p0 = __floats2half2_rn(y[0], y[1]);
    __half2 p1 = __floats2half2_rn(y[2], y[3]);
    __half2 p2 = __floats2half2_rn(y[4], y[5]);
    __half2 p3 = __floats2half2_rn(y[6], y[7]);
    __half2 p4 = __floats2half2_rn(y[8], y[9]);
    uint4 o;
    o.x = *reinterpret_cast<unsigned*>(&p0);
    o.y = *reinterpret_cast<unsigned*>(&p1);
    o.z = *reinterpret_cast<unsigned*>(&p2);
    o.w = *reinterpret_cast<unsigned*>(&p3);
    *reinterpret_cast<uint4*>(row) = o;
    *reinterpret_cast<unsigned*>(row + 8) = *reinterpret_cast<unsigned*>(&p4);
}

// ---------- 3: proj1 (8 lanes/node) + perm build (deg packed) + counts + cursor reset ----------
__global__ void k_proj1(const float* __restrict__ h, const float* __restrict__ W1,
                        const int* __restrict__ ng) {
    __shared__ float sW[FINc * DIMc];
    for (int t = threadIdx.x; t < FINc * DIMc; t += blockDim.x) sW[t] = W1[t];
    __syncthreads();

    int gtid = blockIdx.x * blockDim.x + threadIdx.x;   // grid sized exactly Nn*8
    int i = gtid >> 3;
    int sub8 = gtid & 7;

    const float4* hp = reinterpret_cast<const float4*>(h + (size_t)i * FINc + sub8 * 8);
    float4 a = __ldg(hp);
    float4 b = __ldg(hp + 1);

    float acc[DIMc];
    const float* w = sW + (sub8 * 8) * DIMc;
    #pragma unroll
    for (int j = 0; j < DIMc; j++) {
        float v;
        v  = a.x * w[0 * DIMc + j];
        v += a.y * w[1 * DIMc + j];
        v += a.z * w[2 * DIMc + j];
        v += a.w * w[3 * DIMc + j];
        v += b.x * w[4 * DIMc + j];
        v += b.y * w[5 * DIMc + j];
        v += b.z * w[6 * DIMc + j];
        v += b.w * w[7 * DIMc + j];
        acc[j] = v;
    }
    #pragma unroll
    for (int off = 4; off > 0; off >>= 1) {
        #pragma unroll
        for (int j = 0; j < DIMc; j++)
            acc[j] += __shfl_down_sync(0xffffffffu, acc[j], off, 8);
    }

    if (sub8 == 0) {
        store_row10(g_ha + (size_t)i * RSTRIDE, acc);
        atomicAdd(&g_cnt[ng[i]], 1.0f);
        int d = min(g_cursor[i], DEGMAX);
        g_cursor[i] = 0;                              // reset for next call
        int r = atomicAdd(&g_dcur[d], 1);
        g_perm[r] = i | (d << 20);                    // pack degree
    }
}

// ---------- 4-8: fused layer, pair-split MLP ----------
template <int PING, bool LAST>
__global__ void __launch_bounds__(256) k_layer(
        const float* __restrict__ b1, const float* __restrict__ W2,
        const float* __restrict__ b2, const float* __restrict__ l,
        const float* __restrict__ W1n, const int* __restrict__ ng) {
    const __half* __restrict__ yin = (PING == 0) ? g_ha : g_hb;
    __half* __restrict__       yout = (PING == 0) ? g_hb : g_ha;

    __shared__ float sW2[DIMc * DIMc], sW1n[DIMc * DIMc], sb1[DIMc], sb2[DIMc], sl[DIMc];
    int t = threadIdx.x;
    if (t < DIMc * DIMc) {
        sW2[t] = W2[t];
        if (!LAST) sW1n[t] = W1n[t];
    }
    if (t < DIMc) { sb1[t] = b1[t]; sb2[t] = b2[t]; sl[t] = l[t]; }
    __syncthreads();

    int lane = t & 31;
    int warp_global = (blockIdx.x * blockDim.x + t) >> 5;
    int sub = lane & 1;
    int idx = warp_global * 16 + (lane >> 1);

    int i, deg;
    if (idx < Nn) {
        int pv = __ldg(&g_perm[idx]);
        i = pv & 0xFFFFF;
        deg = pv >> 20;
    } else {
        i = Nn;                                   // dummy zero row
        deg = 0;
    }

    size_t e0 = (size_t)i * CSTR;
    int iters = (deg + 7) >> 3;
    int itersW = __reduce_max_sync(0xffffffffu, iters);

    float acc[8] = {0, 0, 0, 0, 0, 0, 0, 0};
    add8(acc, __ldg(reinterpret_cast<const uint4*>(yin + (size_t)i * RSTRIDE + sub * 8)));

    const int baselane = lane & ~1;
    const size_t cbase = e0 + sub * 4;

    for (int it = 0; it < itersW; ++it) {
        bool live = (it < iters);
        size_t cidx = live ? (cbase + (size_t)it * 8) : ((size_t)Nn * CSTR);
        int4 idv = __ldg(reinterpret_cast<const int4*>(g_csr + cidx));
        int id[4] = {idv.x, idv.y, idv.z, idv.w};

        uint4 r[8];
        #pragma unroll
        for (int k = 0; k < 8; ++k) {
            int s = __shfl_sync(0xffffffffu, id[k & 3], baselane + (k >> 2));
            if (!live) s = Nn;
            r[k] = __ldg(reinterpret_cast<const uint4*>(
                    yin + (size_t)s * RSTRIDE + sub * 8));
        }
        hadd4(r[0], r[1]);
        hadd4(r[2], r[3]);
        hadd4(r[4], r[5]);
        hadd4(r[6], r[7]);
        hadd4(r[0], r[2]);
        hadd4(r[4], r[6]);
        hadd4(r[0], r[4]);
        add8(acc, r[0]);
    }

    // ---- pair-split MLP: exchange raw partial sums, each lane does 5 output cols ----
    float racc[8];
    #pragma unroll
    for (int k = 0; k < 8; k++) racc[k] = __shfl_xor_sync(0xffffffffu, acc[k], 1);

    // full u[10] on BOTH lanes (even holds dims0-7 in acc, dims8-9 arrive via racc[0..1];
    // odd holds dims8-9 in acc[0..1], dims0-7 arrive via racc)
    float u[DIMc];
    #pragma unroll
    for (int k = 0; k < 8; k++) {
        float a = sub ? racc[k] : acc[k];
        u[k] = fmaxf(a + sb1[k], 0.0f);
    }
    {
        float a8 = sub ? acc[0] : racc[0];
        float a9 = sub ? acc[1] : racc[1];
        u[8] = fmaxf(a8 + sb1[8], 0.0f);
        u[9] = fmaxf(a9 + sb1[9], 0.0f);
    }

    // x columns: lane computes j = sub*5 + jj  (bank-conflict-free: addrs differ by 20B)
    float xp[5];
    #pragma unroll
    for (int jj = 0; jj < 5; jj++) {
        int j = sub * 5 + jj;
        float tv = sb2[j];
        #pragma unroll
        for (int k = 0; k < DIMc; k++) tv += u[k] * sW2[k * DIMc + j];
        xp[jj] = fmaxf(tv, 0.0f);
    }

    // readout dot, combined across the pair
    float dot = 0.0f;
    #pragma unroll
    for (int jj = 0; jj < 5; jj++) dot += xp[jj] * sl[sub * 5 + jj];
    dot += __shfl_xor_sync(0xffffffffu, dot, 1);
    if (sub == 0 && i < Nn) atomicAdd(&g_sacc[ng[i]], dot);

    if (!LAST) {
        // reconstruct full x[10] on both lanes (static indices, predicated selects)
        float x[DIMc];
        #pragma unroll
        for (int jj = 0; jj < 5; jj++) {
            float xr = __shfl_xor_sync(0xffffffffu, xp[jj], 1);
            x[jj]     = sub ? xr : xp[jj];
            x[5 + jj] = sub ? xp[jj] : xr;
        }
        // projection: lane computes j2 = sub*5 + jj
        float ynp[5];
        #pragma unroll
        for (int jj = 0; jj < 5; jj++) {
            int j2 = sub * 5 + jj;
            float v = 0.0f;
            #pragma unroll
            for (int j = 0; j < DIMc; j++) v += x[j] * sW1n[j * DIMc + j2];
            ynp[jj] = v;
        }
        // assemble full row on even lane and store
        float yn[DIMc];
        #pragma unroll
        for (int jj = 0; jj < 5; jj++) {
            float ynr = __shfl_xor_sync(0xffffffffu, ynp[jj], 1);
            yn[jj]     = sub ? ynr : ynp[jj];
            yn[5 + jj] = sub ? ynp[jj] : ynr;
        }
        if (sub == 0 && i < Nn) store_row10(yout + (size_t)i * RSTRIDE, yn);
    }
}

// ---------- 9: final (reads + resets accumulators) ----------
__global__ void k_final(float* __restrict__ out) {
    int g = blockIdx.x * blockDim.x + threadIdx.x;
    if (g < Gg) {
        float c = fmaxf(g_cnt[g], 1.0f);
        float s = g_sacc[g] / c;
        out[g] = 1.0f / (1.0f + expf(-s));
        g_sacc[g] = 0.0f;                 // reset for next call
        g_cnt[g] = 0.0f;
    }
}

extern "C" void kernel_launch(void* const* d_in, const int* in_sizes, int n_in,
                              void* d_out, int out_size) {
    const float* h   = (const float*)d_in[0];
    const int*   src = (const int*)d_in[1];
    const int*   dst = (const int*)d_in[2];
    const int*   ng  = (const int*)d_in[3];
    const float* W1[5]; const float* b1[5]; const float* W2[5];
    const float* b2[5]; const float* ll[5];
    for (int i = 0; i < 5; i++) {
        W1[i] = (const float*)d_in[4 + 5 * i + 0];
        b1[i] = (const float*)d_in[4 + 5 * i + 1];
        W2[i] = (const float*)d_in[4 + 5 * i + 2];
        b2[i] = (const float*)d_in[4 + 5 * i + 3];
        ll[i] = (const float*)d_in[4 + 5 * i + 4];
    }
    float* out = (float*)d_out;

    const int TB = 256;
    int e2blk = (Ee / 2 + TB - 1) / TB;
    int nblk  = (Nn + TB - 1) / TB;
    int gblk  = (Gg + TB - 1) / TB;
    int pblk  = (Nn * 8) / TB;                 // exact: 15625
    int lblk  = (Nn * 2 + TB - 1) / TB;        // pair-per-node

    k_scatter<<<e2blk, TB>>>(src, dst);                                       // 1
    k_post<<<nblk, TB>>>();                                                   // 2
    k_proj1<<<pblk, TB>>>(h, W1[0], ng);                                      // 3
    k_layer<0, false><<<lblk, TB>>>(b1[0], W2[0], b2[0], ll[0], W1[1], ng);   // 4 <- profiled
    k_layer<1, false><<<lblk, TB>>>(b1[1], W2[1], b2[1], ll[1], W1[2], ng);   // 5
    k_layer<0, false><<<lblk, TB>>>(b1[2], W2[2], b2[2], ll[2], W1[3], ng);   // 6
    k_layer<1, false><<<lblk, TB>>>(b1[3], W2[3], b2[3], ll[3], W1[4], ng);   // 7
    k_layer<0, true ><<<lblk, TB>>>(b1[4], W2[4], b2[4], ll[4], nullptr, ng); // 8
    k_final<<<gblk, TB>>>(out);                                               // 9
}

// round 9
// speedup vs baseline: 1.0576x; 1.0576x over previous
#include <cuda_runtime.h>
#include <cuda_fp16.h>
#include <math.h>

#define Nn 500000
#define Ee 16000000
#define Gg 5000
#define DIMc 10
#define FINc 64
#define RSTRIDE 16                                 // halves per feature row (32 B)
#define CSTR 128                                   // fixed CSR slots per node
#define DEGMAX (CSTR - 8)

// ---------- static device scratch (all state returns to initial value each call) ----------
__device__ __align__(16) __half g_ha[((size_t)Nn + 1) * RSTRIDE];
__device__ __align__(16) __half g_hb[((size_t)Nn + 1) * RSTRIDE];
__device__ int   g_cursor[Nn + 1];                 // zero before scatter; re-zeroed in proj1
__device__ __align__(16) int g_csr[((size_t)Nn + 1) * CSTR];
__device__ int   g_perm[Nn];                       // node id | (deg << 20)
__device__ int   g_dbin[256];                      // zero; re-zeroed in post's last block
__device__ int   g_dcur[256];                      // recomputed every call
__device__ int   g_done;                           // zero; re-zeroed in post's last block
__device__ float g_sacc[Gg];                       // zero; re-zeroed in final
__device__ float g_cnt[Gg];                        // zero; re-zeroed in final

// ---------- 1: scatter edges into fixed-stride CSR ----------
__global__ void k_scatter(const int* __restrict__ src, const int* __restrict__ dst) {
    int e2 = blockIdx.x * blockDim.x + threadIdx.x;   // Ee % 2 == 0
    if ((size_t)e2 * 2 >= Ee) return;
    int2 d = __ldg(reinterpret_cast<const int2*>(dst) + e2);
    int2 s = __ldg(reinterpret_cast<const int2*>(src) + e2);
    int p0 = atomicAdd(&g_cursor[d.x], 1);
    g_csr[(size_t)d.x * CSTR + min(p0, CSTR - 1)] = s.x;
    int p1 = atomicAdd(&g_cursor[d.y], 1);
    g_csr[(size_t)d.y * CSTR + min(p1, CSTR - 1)] = s.y;
}

// ---------- 2: per-node post: pad CSR rows + degree-bin hist; last block scans bins ----------
// Bucket bases are DESCENDING-degree (LPT): heavy nodes first in g_perm.
__global__ void k_post() {
    __shared__ int shist[256];
    __shared__ int slast;
    int t = threadIdx.x;                 // blockDim == 256
    shist[t] = 0;
    __syncthreads();
    int i = blockIdx.x * blockDim.x + t;
    if (i < Nn) {
        int d = min(g_cursor[i], DEGMAX);
        atomicAdd(&shist[d], 1);
        int pd = (d + 7) & ~7;
        size_t base = (size_t)i * CSTR;
        for (int q = d; q < pd; q++) g_csr[base + q] = Nn;   // dummy zero row
    }
    __syncthreads();
    if (shist[t]) atomicAdd(&g_dbin[t], shist[t]);
    __threadfence();                     // release dbin updates
    __syncthreads();
    if (t == 0) slast = (atomicAdd(&g_done, 1) == (int)gridDim.x - 1) ? 1 : 0;
    __syncthreads();
    if (slast) {                         // last arriving block: scan bins, reset state
        __threadfence();                 // acquire all dbin updates
        __shared__ int sb[256];
        int v = g_dbin[t];
        sb[t] = v;
        __syncthreads();
        #pragma unroll
        for (int off = 1; off < 256; off <<= 1) {
            int q = (t >= off) ? sb[t - off] : 0;
            __syncthreads();
            sb[t] += q;
            __syncthreads();
        }
        // descending-degree base: nodes with degree > t come first
        g_dcur[t] = sb[255] - sb[t];
        g_dbin[t] = 0;                   // reset for next call
        if (t == 0) g_done = 0;
    }
}

// ---------- helpers ----------
__device__ __forceinline__ void hadd4(uint4& a, const uint4 b) {
    *reinterpret_cast<__half2*>(&a.x) = __hadd2(*reinterpret_cast<const __half2*>(&a.x),
                                                *reinterpret_cast<const __half2*>(&b.x));
    *reinterpret_cast<__half2*>(&a.y) = __hadd2(*reinterpret_cast<const __half2*>(&a.y),
                                                *reinterpret_cast<const __half2*>(&b.y));
    *reinterpret_cast<__half2*>(&a.z) = __hadd2(*reinterpret_cast<const __half2*>(&a.z),
                                                *reinterpret_cast<const __half2*>(&b.z));
    *reinterpret_cast<__half2*>(&a.w) = __hadd2(*reinterpret_cast<const __half2*>(&a.w),
                                                *reinterpret_cast<const __half2*>(&b.w));
}

__device__ __forceinline__ void add8(float* acc, uint4 v) {
    float2 f;
    f = __half22float2(*reinterpret_cast<__half2*>(&v.x)); acc[0] += f.x; acc[1] += f.y;
    f = __half22float2(*reinterpret_cast<__half2*>(&v.y)); acc[2] += f.x; acc[3] += f.y;
    f = __half22float2(*reinterpret_cast<__half2*>(&v.z)); acc[4] += f.x; acc[5] += f.y;
    f = __half22float2(*reinterpret_cast<__half2*>(&v.w)); acc[6] += f.x; acc[7] += f.y;
}

__device__ __forceinline__ void store_row10(__half* row, const float* y) {
    __half2 p0 = __floats2half2_rn(y[0], y[1]);
    __half2 p1 = __floats2half2_rn(y[2], y[3]);
    __half2 p2 = __floats2half2_rn(y[4], y[5]);
    __half2 p3 = __floats2half2_rn(y[6], y[7]);
    __half2 p4 = __floats2half2_rn(y[8], y[9]);
    uint4 o;
    o.x = *reinterpret_cast<unsigned*>(&p0);
    o.y = *reinterpret_cast<unsigned*>(&p1);
    o.z = *reinterpret_cast<unsigned*>(&p2);
    o.w = *reinterpret_cast<unsigned*>(&p3);
    *reinterpret_cast<uint4*>(row) = o;
    *reinterpret_cast<unsigned*>(row + 8) = *reinterpret_cast<unsigned*>(&p4);
}

// ---------- 3: proj1 (8 lanes/node) + perm build (deg packed) + counts + cursor reset ----------
__global__ void k_proj1(const float* __restrict__ h, const float* __restrict__ W1,
                        const int* __restrict__ ng) {
    __shared__ float sW[FINc * DIMc];
    for (int t = threadIdx.x; t < FINc * DIMc; t += blockDim.x) sW[t] = W1[t];
    __syncthreads();

    int gtid = blockIdx.x * blockDim.x + threadIdx.x;   // grid sized exactly Nn*8
    int i = gtid >> 3;
    int sub8 = gtid & 7;

    const float4* hp = reinterpret_cast<const float4*>(h + (size_t)i * FINc + sub8 * 8);
    float4 a = __ldg(hp);
    float4 b = __ldg(hp + 1);

    float acc[DIMc];
    const float* w = sW + (sub8 * 8) * DIMc;
    #pragma unroll
    for (int j = 0; j < DIMc; j++) {
        float v;
        v  = a.x * w[0 * DIMc + j];
        v += a.y * w[1 * DIMc + j];
        v += a.z * w[2 * DIMc + j];
        v += a.w * w[3 * DIMc + j];
        v += b.x * w[4 * DIMc + j];
        v += b.y * w[5 * DIMc + j];
        v += b.z * w[6 * DIMc + j];
        v += b.w * w[7 * DIMc + j];
        acc[j] = v;
    }
    #pragma unroll
    for (int off = 4; off > 0; off >>= 1) {
        #pragma unroll
        for (int j = 0; j < DIMc; j++)
            acc[j] += __shfl_down_sync(0xffffffffu, acc[j], off, 8);
    }

    if (sub8 == 0) {
        store_row10(g_ha + (size_t)i * RSTRIDE, acc);
        atomicAdd(&g_cnt[ng[i]], 1.0f);
        int d = min(g_cursor[i], DEGMAX);
        g_cursor[i] = 0;                              // reset for next call
        int r = atomicAdd(&g_dcur[d], 1);
        g_perm[r] = i | (d << 20);                    // pack degree
    }
}

// ---------- 4-8: fused layer over descending-degree-sorted nodes (R7 MLP form) ----------
template <int PING, bool LAST>
__global__ void __launch_bounds__(256) k_layer(
        const float* __restrict__ b1, const float* __restrict__ W2,
        const float* __restrict__ b2, const float* __restrict__ l,
        const float* __restrict__ W1n, const int* __restrict__ ng) {
    const __half* __restrict__ yin = (PING == 0) ? g_ha : g_hb;
    __half* __restrict__       yout = (PING == 0) ? g_hb : g_ha;

    __shared__ float sW2[DIMc * DIMc], sW1n[DIMc * DIMc], sb1[DIMc], sb2[DIMc], sl[DIMc];
    int t = threadIdx.x;
    if (t < DIMc * DIMc) {
        sW2[t] = W2[t];
        if (!LAST) sW1n[t] = W1n[t];
    }
    if (t < DIMc) { sb1[t] = b1[t]; sb2[t] = b2[t]; sl[t] = l[t]; }
    __syncthreads();

    int lane = t & 31;
    int warp_global = (blockIdx.x * blockDim.x + t) >> 5;
    int sub = lane & 1;
    int idx = warp_global * 16 + (lane >> 1);

    int i, deg;
    if (idx < Nn) {
        int pv = __ldg(&g_perm[idx]);
        i = pv & 0xFFFFF;
        deg = pv >> 20;
    } else {
        i = Nn;                                   // dummy zero row
        deg = 0;
    }

    size_t e0 = (size_t)i * CSTR;
    int iters = (deg + 7) >> 3;
    int itersW = __reduce_max_sync(0xffffffffu, iters);

    float acc[8] = {0, 0, 0, 0, 0, 0, 0, 0};
    add8(acc, __ldg(reinterpret_cast<const uint4*>(yin + (size_t)i * RSTRIDE + sub * 8)));

    const int baselane = lane & ~1;
    const size_t cbase = e0 + sub * 4;

    for (int it = 0; it < itersW; ++it) {
        bool live = (it < iters);
        size_t cidx = live ? (cbase + (size_t)it * 8) : ((size_t)Nn * CSTR);
        int4 idv = __ldg(reinterpret_cast<const int4*>(g_csr + cidx));
        int id[4] = {idv.x, idv.y, idv.z, idv.w};

        uint4 r[8];
        #pragma unroll
        for (int k = 0; k < 8; ++k) {
            int s = __shfl_sync(0xffffffffu, id[k & 3], baselane + (k >> 2));
            if (!live) s = Nn;
            r[k] = __ldg(reinterpret_cast<const uint4*>(
                    yin + (size_t)s * RSTRIDE + sub * 8));
        }
        hadd4(r[0], r[1]);
        hadd4(r[2], r[3]);
        hadd4(r[4], r[5]);
        hadd4(r[6], r[7]);
        hadd4(r[0], r[2]);
        hadd4(r[4], r[6]);
        hadd4(r[0], r[4]);
        add8(acc, r[0]);
    }

    float v8 = __shfl_down_sync(0xffffffffu, acc[0], 1);
    float v9 = __shfl_down_sync(0xffffffffu, acc[1], 1);

    if (sub == 0 && i < Nn) {
        float u[DIMc];
        #pragma unroll
        for (int j = 0; j < 8; j++) u[j] = fmaxf(acc[j] + sb1[j], 0.0f);
        u[8] = fmaxf(v8 + sb1[8], 0.0f);
        u[9] = fmaxf(v9 + sb1[9], 0.0f);

        float x[DIMc];
        #pragma unroll
        for (int j = 0; j < DIMc; j++) {
            float tv = sb2[j];
            #pragma unroll
            for (int k = 0; k < DIMc; k++) tv += u[k] * sW2[k * DIMc + j];
            x[j] = fmaxf(tv, 0.0f);
        }

        float dot = 0.0f;
        #pragma unroll
        for (int j = 0; j < DIMc; j++) dot += x[j] * sl[j];
        atomicAdd(&g_sacc[ng[i]], dot);

        if (!LAST) {
            float yn[DIMc];
            #pragma unroll
            for (int j2 = 0; j2 < DIMc; j2++) {
                float v = 0.0f;
                #pragma unroll
                for (int j = 0; j < DIMc; j++) v += x[j] * sW1n[j * DIMc + j2];
                yn[j2] = v;
            }
            store_row10(yout + (size_t)i * RSTRIDE, yn);
        }
    }
}

// ---------- 9: final (reads + resets accumulators) ----------
__global__ void k_final(float* __restrict__ out) {
    int g = blockIdx.x * blockDim.x + threadIdx.x;
    if (g < Gg) {
        float c = fmaxf(g_cnt[g], 1.0f);
        float s = g_sacc[g] / c;
        out[g] = 1.0f / (1.0f + expf(-s));
        g_sacc[g] = 0.0f;                 // reset for next call
        g_cnt[g] = 0.0f;
    }
}

extern "C" void kernel_launch(void* const* d_in, const int* in_sizes, int n_in,
                              void* d_out, int out_size) {
    const float* h   = (const float*)d_in[0];
    const int*   src = (const int*)d_in[1];
    const int*   dst = (const int*)d_in[2];
    const int*   ng  = (const int*)d_in[3];
    const float* W1[5]; const float* b1[5]; const float* W2[5];
    const float* b2[5]; const float* ll[5];
    for (int i = 0; i < 5; i++) {
        W1[i] = (const float*)d_in[4 + 5 * i + 0];
        b1[i] = (const float*)d_in[4 + 5 * i + 1];
        W2[i] = (const float*)d_in[4 + 5 * i + 2];
        b2[i] = (const float*)d_in[4 + 5 * i + 3];
        ll[i] = (const float*)d_in[4 + 5 * i + 4];
    }
    float* out = (float*)d_out;

    const int TB = 256;
    int e2blk = (Ee / 2 + TB - 1) / TB;
    int nblk  = (Nn + TB - 1) / TB;
    int gblk  = (Gg + TB - 1) / TB;
    int pblk  = (Nn * 8) / TB;                 // exact: 15625
    int lblk  = (Nn * 2 + TB - 1) / TB;        // pair-per-node

    k_scatter<<<e2blk, TB>>>(src, dst);                                       // 1
    k_post<<<nblk, TB>>>();                                                   // 2
    k_proj1<<<pblk, TB>>>(h, W1[0], ng);                                      // 3
    k_layer<0, false><<<lblk, TB>>>(b1[0], W2[0], b2[0], ll[0], W1[1], ng);   // 4 <- profiled
    k_layer<1, false><<<lblk, TB>>>(b1[1], W2[1], b2[1], ll[1], W1[2], ng);   // 5
    k_layer<0, false><<<lblk, TB>>>(b1[2], W2[2], b2[2], ll[2], W1[3], ng);   // 6
    k_layer<1, false><<<lblk, TB>>>(b1[3], W2[3], b2[3], ll[3], W1[4], ng);   // 7
    k_layer<0, true ><<<lblk, TB>>>(b1[4], W2[4], b2[4], ll[4], nullptr, ng); // 8
    k_final<<<gblk, TB>>>(out);                                               // 9
}